// round 14
// baseline (speedup 1.0000x reference)
#include <cuda_runtime.h>
#include <math.h>
#include <complex>

// ---------------- problem constants ----------------
#define TT    16384          // time steps (output rows)
#define BB    512            // batch columns
#define TPAD  16388          // TT + K - 1 (K = 5)
#define NBLK  256            // IIR blocks: block k = rows 64k..64k+63 (block 0 IIR starts row 5)
#define NCG   16             // column groups of 32

// ---------------- device scratch (static, allocation-free) ----------------
__device__ float  g_sd[TPAD];           // noise std-dev per padded time step
__device__ float4 g_u[NBLK * BB];       // zero-state end states per (block,col)
__device__ float4 g_v0[BB];             // initial state v0 = [s4,s3,s2,s1] per col
__device__ int    g_flag[NCG * NBLK];   // release flags, zeroed each replay by k_sd

struct FIX {
    float  m[5 * 16];     // M^j (j=0..4), M = A^64, row-major 4x4   (applied to u)
    float  ma[5 * 16];    // M^i * A^59 (i=0..4)                      (applied to v0, i=k-1)
    float  hf[4 * 64];    // zero-input impulse tables hf_c[i], 64 steps (f32, epilogue)
    double hfd[16];       // hfd[c*4 + (i-28)] = h_c[i], i=28..31 in f64 (u-publish combine)
};

// ---------------- kernel 1: noise std-dev (4 rows per warp) + flag reset ----------------
__global__ __launch_bounds__(256) void k_sd(const float* __restrict__ sig,
                                            float c1, float addc) {
    if (blockIdx.x < NCG)
        g_flag[blockIdx.x * NBLK + threadIdx.x] = 0;

    int lane = threadIdx.x & 31;
    int tbase = blockIdx.x * 32 + (threadIdx.x >> 5) * 4;
    float s[4] = {0.f, 0.f, 0.f, 0.f};
    #pragma unroll
    for (int r = 0; r < 4; r++) {
        int t = tbase + r;
        if (t >= 4 && t < TPAD) {
            const float4* row = (const float4*)(sig + (size_t)(t - 4) * BB);
            float4 a = row[lane], b = row[lane + 32], c = row[lane + 64], d = row[lane + 96];
            s[r] = ((a.x + a.y) + (a.z + a.w)) + ((b.x + b.y) + (b.z + b.w))
                 + ((c.x + c.y) + (c.z + c.w)) + ((d.x + d.y) + (d.z + d.w));
        }
    }
    #pragma unroll
    for (int o = 16; o; o >>= 1) {
        #pragma unroll
        for (int r = 0; r < 4; r++) s[r] += __shfl_down_sync(0xffffffffu, s[r], o);
    }
    if (lane == 0) {
        #pragma unroll
        for (int r = 0; r < 4; r++) {
            int t = tbase + r;
            if (t < TPAD) g_sd[t] = sqrtf(fmaf(c1, s[r] * (1.f / 512.f), addc));
        }
    }
}

// 4x4 matvec helper (row-major m), accumulate into (r1..r4)
#define MV4(m, x1, x2, x3, x4, r1, r2, r3, r4)                        \
    do {                                                              \
        r1 = fmaf((m)[0],  x1, r1); r1 = fmaf((m)[1],  x2, r1);       \
        r1 = fmaf((m)[2],  x3, r1); r1 = fmaf((m)[3],  x4, r1);       \
        r2 = fmaf((m)[4],  x1, r2); r2 = fmaf((m)[5],  x2, r2);       \
        r2 = fmaf((m)[6],  x3, r2); r2 = fmaf((m)[7],  x4, r2);       \
        r3 = fmaf((m)[8],  x1, r3); r3 = fmaf((m)[9],  x2, r3);       \
        r3 = fmaf((m)[10], x3, r3); r3 = fmaf((m)[11], x4, r3);       \
        r4 = fmaf((m)[12], x1, r4); r4 = fmaf((m)[13], x2, r4);       \
        r4 = fmaf((m)[14], x3, r4); r4 = fmaf((m)[15], x4, r4);       \
    } while (0)

// zero-input dot: sum_c hf_c[i] * v_c  (f32, single-amplified paths only)
#define HDOT(P, i, v1, v2, v3, v4)                                     \
    ( fmaf((P).hf[3 * 64 + (i)], v4,                                   \
      fmaf((P).hf[2 * 64 + (i)], v3,                                   \
      fmaf((P).hf[1 * 64 + (i)], v2, (P).hf[0 * 64 + (i)] * v1))) )

// ---------------- fused kernel: FIR -> {half-scans (w0,w1) || reconstruct (w2)} -> exact out ----
__global__ __launch_bounds__(256) void k_fused(const float* __restrict__ sig,
                                               const float* __restrict__ noise,
                                               float* __restrict__ out, FIX P,
                                               float b0, float b1, float b2, float b3, float b4,
                                               float na1, float na2, float na3, float na4) {
    __shared__ float nz[32][69];   // noise [col][j], stride 69 -> conflict-free transpose
    __shared__ float sg[68][33];   // signal [j][col]
    __shared__ float st[64][33];   // s tile -> overwritten with half-local zero-state outputs
    __shared__ float sds[68];
    __shared__ float vv[4][33];    // reconstructed entering state per col
    __shared__ float sua[4][33];   // first-half zero-state end state per col
    int tx = threadIdx.x, ty = threadIdx.y;
    int cg = blockIdx.x, k = blockIdx.y;
    int col0 = cg * 32;
    int t0   = k * 64;

    // ---- load tiles (fixed-trip, unrolled) ----
    #pragma unroll
    for (int i = 0; i < 4; i++) {
        int c = ty * 4 + i;
        const float* nrow = noise + (size_t)(col0 + c) * TPAD + t0;
        nz[c][tx]      = nrow[tx];
        nz[c][tx + 32] = nrow[tx + 32];
        if (tx < 4) nz[c][tx + 64] = nrow[tx + 64];
    }
    #pragma unroll
    for (int j = 0; j < 9; j++) {
        int r = ty + 8 * j;
        if (r < 68) {
            int trow = t0 - 4 + r;
            sg[r][tx] = (trow >= 0) ? sig[(size_t)trow * BB + col0 + tx] : 0.f;
        }
    }
    int tid = ty * 32 + tx;
    if (tid < 68) sds[tid] = g_sd[t0 + tid];
    __syncthreads();

    // ---- FIR: 12-value window -> 8 consecutive rows per thread ----
    float xv[12];
    #pragma unroll
    for (int j = 0; j < 12; j++) {
        int jj = 8 * ty + j;
        xv[j] = fmaf(sds[jj], nz[tx][jj], sg[jj][tx]);
    }
    #pragma unroll
    for (int i = 0; i < 8; i++) {
        float acc = b0 * xv[i];
        acc = fmaf(b1, xv[i + 1], acc);
        acc = fmaf(b2, xv[i + 2], acc);
        acc = fmaf(b3, xv[i + 3], acc);
        acc = fmaf(b4, xv[i + 4], acc);
        st[8 * ty + i][tx] = acc;
    }
    __syncthreads();

    bool kz = (k == 0);
    if (ty == 0) {
        // ---- first-half zero-state scan (rows 0..31); k==0: rows 0..4 zeroed, stores skipped ----
        float p1 = st[1][tx], p2 = st[2][tx], p3 = st[3][tx], p4 = st[4][tx];
        float y1 = 0.f, y2 = 0.f, y3 = 0.f, y4 = 0.f;
        #pragma unroll
        for (int i = 0; i < 32; i++) {
            float sv = st[i][tx];
            bool skip = kz && (i < 5);
            if (skip) sv = 0.f;
            float t = fmaf(na4, y4, sv);
            t = fmaf(na3, y3, t);
            t = fmaf(na2, y2, t);
            float y = fmaf(na1, y1, t);
            if (!skip) st[i][tx] = y;
            y4 = y3; y3 = y2; y2 = y1; y1 = y;
        }
        sua[0][tx] = y1; sua[1][tx] = y2; sua[2][tx] = y3; sua[3][tx] = y4;
        if (kz)
            g_v0[col0 + tx] = make_float4(p4, p3, p2, p1);
        asm volatile("bar.sync 1, 64;" ::: "memory");
    } else if (ty == 1) {
        // ---- second-half zero-state scan (rows 32..63), state local to row 32 ----
        float y1 = 0.f, y2 = 0.f, y3 = 0.f, y4 = 0.f;
        #pragma unroll
        for (int i = 32; i < 64; i++) {
            float sv = st[i][tx];
            float t = fmaf(na4, y4, sv);
            t = fmaf(na3, y3, t);
            t = fmaf(na2, y2, t);
            float y = fmaf(na1, y1, t);
            st[i][tx] = y;
            y4 = y3; y3 = y2; y2 = y1; y1 = y;
        }
        asm volatile("bar.sync 1, 64;" ::: "memory");
        // ---- combine in f64 (kills the double-amplified rounding path):
        // u_c = zs2_end_c + zi(ua) at rows 63..60, h-coeffs in f64
        double A1 = (double)sua[0][tx], A2 = (double)sua[1][tx];
        double A3 = (double)sua[2][tx], A4 = (double)sua[3][tx];
        double u1 = (double)y1 + P.hfd[0*4+3]*A1 + P.hfd[1*4+3]*A2 + P.hfd[2*4+3]*A3 + P.hfd[3*4+3]*A4;
        double u2 = (double)y2 + P.hfd[0*4+2]*A1 + P.hfd[1*4+2]*A2 + P.hfd[2*4+2]*A3 + P.hfd[3*4+2]*A4;
        double u3 = (double)y3 + P.hfd[0*4+1]*A1 + P.hfd[1*4+1]*A2 + P.hfd[2*4+1]*A3 + P.hfd[3*4+1]*A4;
        double u4 = (double)y4 + P.hfd[0*4+0]*A1 + P.hfd[1*4+0]*A2 + P.hfd[2*4+0]*A3 + P.hfd[3*4+0]*A4;
        g_u[k * BB + col0 + tx] = make_float4((float)u1, (float)u2, (float)u3, (float)u4);
        __threadfence();
        __syncwarp();
        if (tx == 0) atomicExch(&g_flag[cg * NBLK + k], 1);
    } else if (ty == 2) {
        // ---- concurrent: reconstruct entering state v_k from predecessors ----
        if (kz) {
            vv[0][tx] = st[4][tx];    // rows 1..4 stay raw (warp0 skips their stores)
            vv[1][tx] = st[3][tx];
            vv[2][tx] = st[2][tx];
            vv[3][tx] = st[1][tx];
        } else {
            if (tx < 5) {
                int idx = k - 1 - tx;
                if (idx >= 0) {
                    volatile int* fp = (volatile int*)&g_flag[cg * NBLK + idx];
                    while (*fp == 0) __nanosleep(32);
                }
            }
            __syncwarp();
            __threadfence();

            float v1 = 0.f, v2 = 0.f, v3 = 0.f, v4 = 0.f;
            #pragma unroll
            for (int j = 0; j <= 4; j++) {
                int idx = k - 1 - j;
                if (idx < 0) break;
                float4 u = __ldcg(&g_u[idx * BB + col0 + tx]);
                const float* m = P.m + j * 16;
                MV4(m, u.x, u.y, u.z, u.w, v1, v2, v3, v4);
            }
            if (k <= 5) {
                float4 u = __ldcg(&g_v0[col0 + tx]);
                const float* m = P.ma + (k - 1) * 16;
                MV4(m, u.x, u.y, u.z, u.w, v1, v2, v3, v4);
            }
            vv[0][tx] = v1; vv[1][tx] = v2; vv[2][tx] = v3; vv[3][tx] = v4;
        }
    }
    __syncthreads();   // st = half-local zs outputs; vv = entering state; sua = half state

    // ---- epilogue: corrections via impulse tables (single-amplified, f32 ok) ----
    float v1 = vv[0][tx], v2 = vv[1][tx], v3 = vv[2][tx], v4 = vv[3][tx];
    float a1 = 0.f, a2 = 0.f, a3 = 0.f, a4 = 0.f;
    if (ty >= 4) {   // second half also corrects with ua
        a1 = sua[0][tx]; a2 = sua[1][tx]; a3 = sua[2][tx]; a4 = sua[3][tx];
    }
    #pragma unroll
    for (int i = 0; i < 8; i++) {
        int tt = 8 * ty + i;
        float val;
        if (kz && tt < 5) {
            val = st[tt][tx];                 // out rows 0..4 = s rows 0..4
        } else {
            int ii = kz ? tt - 5 : tt;        // steps since block start (warp-uniform)
            float add = HDOT(P, ii, v1, v2, v3, v4);
            if (ty >= 4)                      // + zi of first-half state, tt-32 steps past row 32
                add += HDOT(P, tt - 32, a1, a2, a3, a4);
            val = st[tt][tx] + add;
        }
        out[(size_t)(t0 + tt) * BB + col0 + tx] = val;
    }
}

// ---------------- host: Butterworth design (exact replica of reference, f64) ----------------
static void compute_butter(double* bc, double* ac) {
    const double PI = 3.14159265358979323846264338327950288;
    const int order = 4;
    const double wn = 25e9 / (0.5 / 1e-12);   // 0.05
    double warped = 4.0 * tan(PI * wn / 2.0);
    std::complex<double> p[4];
    for (int k = 1; k <= order; k++) {
        double ang = PI * (2.0 * k + order - 1.0) / (2.0 * order);
        p[k - 1] = warped * std::complex<double>(cos(ang), sin(ang));
    }
    double gain = warped * warped * warped * warped;
    std::complex<double> fs2(4.0, 0.0);
    std::complex<double> pz[4], prod(1.0, 0.0);
    for (int i = 0; i < 4; i++) { pz[i] = (fs2 + p[i]) / (fs2 - p[i]); prod *= (fs2 - p[i]); }
    double gz = gain * std::real(std::complex<double>(1.0, 0.0) / prod);
    const double binom[5] = {1, 4, 6, 4, 1};
    for (int i = 0; i < 5; i++) bc[i] = gz * binom[i];
    std::complex<double> c[5] = {{1,0},{0,0},{0,0},{0,0},{0,0}};
    for (int i = 0; i < 4; i++)
        for (int j = i + 1; j >= 1; j--)
            c[j] -= pz[i] * c[j - 1];
    for (int i = 0; i < 5; i++) ac[i] = std::real(c[i]);
}

// A^n (companion of the IIR state [y1,y2,y3,y4]) via column simulation, f64
static void apow(const double* ac, int n, double* A) {
    for (int c = 0; c < 4; c++) {
        double y1 = (c == 0), y2 = (c == 1), y3 = (c == 2), y4 = (c == 3);
        for (int it = 0; it < n; it++) {
            double y = -(ac[1] * y1 + ac[2] * y2 + ac[3] * y3 + ac[4] * y4);
            y4 = y3; y3 = y2; y2 = y1; y1 = y;
        }
        A[0 * 4 + c] = y1; A[1 * 4 + c] = y2; A[2 * 4 + c] = y3; A[3 * 4 + c] = y4;
    }
}

static void matmul4(const double* X, const double* Y, double* Z) {
    for (int r = 0; r < 4; r++)
        for (int c = 0; c < 4; c++) {
            double acc = 0.0;
            for (int t = 0; t < 4; t++) acc += X[r * 4 + t] * Y[t * 4 + c];
            Z[r * 4 + c] = acc;
        }
}

extern "C" void kernel_launch(void* const* d_in, const int* in_sizes, int n_in,
                              void* d_out, int out_size) {
    const float* sig   = (const float*)d_in[0];   // (16384, 512) f32
    const float* noise = (const float*)d_in[1];   // (512, 1, 16388) f32
    float* out = (float*)d_out;                   // (16384, 512) f32

    double bc[5], ac[5];
    compute_butter(bc, ac);

    static FIX fx;
    // zero-input impulse tables hf_c[i], 64 steps (f64 master; f32 table + f64 rows 28..31)
    for (int c = 0; c < 4; c++) {
        double y1 = (c == 0), y2 = (c == 1), y3 = (c == 2), y4 = (c == 3);
        for (int i = 0; i < 64; i++) {
            double y = -(ac[1] * y1 + ac[2] * y2 + ac[3] * y3 + ac[4] * y4);
            fx.hf[c * 64 + i] = (float)y;
            if (i >= 28 && i <= 31) fx.hfd[c * 4 + (i - 28)] = y;
            y4 = y3; y3 = y2; y2 = y1; y1 = y;
        }
    }
    double A59[16], A64[16], Mj[16], tmp[16];
    apow(ac, 59, A59);
    apow(ac, 64, A64);
    for (int i = 0; i < 16; i++) Mj[i] = (i % 5 == 0) ? 1.0 : 0.0;   // M^0 = I
    for (int j = 0; j <= 4; j++) {
        for (int i = 0; i < 16; i++) fx.m[j * 16 + i] = (float)Mj[i];
        matmul4(Mj, A59, tmp);                   // ma[j] = M^j * A^59
        for (int i = 0; i < 16; i++) fx.ma[j * 16 + i] = (float)tmp[i];
        matmul4(Mj, A64, tmp);                   // Mj = M^{j+1}
        for (int i = 0; i < 16; i++) Mj[i] = tmp[i];
    }

    const double Qc = 1.602176563e-19, KBc = 1.3806488e-23, Tk = 300.0;
    const double BR = 5e10, DARK = 1e-10, RL = 1e6;
    double C1  = 2.0 * Qc * BR;
    double ADD = C1 * DARK + 4.0 * KBc * Tk * BR / RL;

    float na1 = (float)(-ac[1]), na2 = (float)(-ac[2]);
    float na3 = (float)(-ac[3]), na4 = (float)(-ac[4]);

    k_sd   <<<(TPAD + 31) / 32, 256>>>(sig, (float)C1, (float)ADD);
    k_fused<<<dim3(NCG, NBLK), dim3(32, 8)>>>(sig, noise, out, fx,
              (float)bc[0], (float)bc[1], (float)bc[2], (float)bc[3], (float)bc[4],
              na1, na2, na3, na4);
}

// round 15
// speedup vs baseline: 1.1202x; 1.1202x over previous
#include <cuda_runtime.h>
#include <math.h>
#include <complex>

// ---------------- problem constants ----------------
#define TT    16384          // time steps (output rows)
#define BB    512            // batch columns
#define TPAD  16388          // TT + K - 1 (K = 5)
#define NBLK  256            // IIR blocks: block k = rows 64k..64k+63 (block 0 IIR starts row 5)
#define NCG   8              // column groups of 64

// ---------------- device scratch (static, allocation-free) ----------------
__device__ float  g_sd[TPAD];           // noise std-dev per padded time step
__device__ float4 g_u[NBLK * BB];       // zero-state end states per (block,col)
__device__ float4 g_v0[BB];             // initial state v0 = [s4,s3,s2,s1] per col
__device__ int    g_flag[NCG * NBLK];   // release flags, zeroed each replay by k_sd

struct FIX {
    float  m[5 * 16];     // M^j (j=0..4), M = A^64, row-major 4x4   (applied to u)
    float  ma[5 * 16];    // M^i * A^59 (i=0..4)                      (applied to v0, i=k-1)
    float  hf[4 * 64];    // zero-input impulse tables hf_c[i], 64 steps (f32, epilogue)
    double hfd[16];       // hfd[c*4 + (i-28)] = h_c[i], i=28..31 in f64 (u-publish combine)
};

// ---------------- kernel 1: noise std-dev (2 rows per warp) + flag reset ----------------
__global__ __launch_bounds__(256) void k_sd(const float* __restrict__ sig,
                                            float c1, float addc) {
    if (blockIdx.x < NCG)
        g_flag[blockIdx.x * NBLK + threadIdx.x] = 0;

    int lane = threadIdx.x & 31;
    int t0 = blockIdx.x * 16 + (threadIdx.x >> 5) * 2;
    if (t0 >= TPAD) return;
    float s0 = 0.f, s1 = 0.f;
    if (t0 >= 4) {
        const float4* r0 = (const float4*)(sig + (size_t)(t0 - 4) * BB);
        float4 a = r0[lane], b = r0[lane + 32], c = r0[lane + 64], d = r0[lane + 96];
        s0 = ((a.x + a.y) + (a.z + a.w)) + ((b.x + b.y) + (b.z + b.w))
           + ((c.x + c.y) + (c.z + c.w)) + ((d.x + d.y) + (d.z + d.w));
    }
    int t1 = t0 + 1;
    if (t1 >= 4 && t1 < TPAD) {
        const float4* r1 = (const float4*)(sig + (size_t)(t1 - 4) * BB);
        float4 a = r1[lane], b = r1[lane + 32], c = r1[lane + 64], d = r1[lane + 96];
        s1 = ((a.x + a.y) + (a.z + a.w)) + ((b.x + b.y) + (b.z + b.w))
           + ((c.x + c.y) + (c.z + c.w)) + ((d.x + d.y) + (d.z + d.w));
    }
    #pragma unroll
    for (int o = 16; o; o >>= 1) {
        s0 += __shfl_down_sync(0xffffffffu, s0, o);
        s1 += __shfl_down_sync(0xffffffffu, s1, o);
    }
    if (lane == 0) {
        g_sd[t0] = sqrtf(fmaf(c1, s0 * (1.f / 512.f), addc));
        if (t1 < TPAD) g_sd[t1] = sqrtf(fmaf(c1, s1 * (1.f / 512.f), addc));
    }
}

// 4x4 matvec (row-major m), accumulate into (r1..r4)
#define MV4(m, x1, x2, x3, x4, r1, r2, r3, r4)                        \
    do {                                                              \
        r1 = fmaf((m)[0],  x1, r1); r1 = fmaf((m)[1],  x2, r1);       \
        r1 = fmaf((m)[2],  x3, r1); r1 = fmaf((m)[3],  x4, r1);       \
        r2 = fmaf((m)[4],  x1, r2); r2 = fmaf((m)[5],  x2, r2);       \
        r2 = fmaf((m)[6],  x3, r2); r2 = fmaf((m)[7],  x4, r2);       \
        r3 = fmaf((m)[8],  x1, r3); r3 = fmaf((m)[9],  x2, r3);       \
        r3 = fmaf((m)[10], x3, r3); r3 = fmaf((m)[11], x4, r3);       \
        r4 = fmaf((m)[12], x1, r4); r4 = fmaf((m)[13], x2, r4);       \
        r4 = fmaf((m)[14], x3, r4); r4 = fmaf((m)[15], x4, r4);       \
    } while (0)

// zero-input dot: sum_c hf_c[i] * v_c (scalar)
#define HDOT(P, i, v1, v2, v3, v4)                                     \
    ( fmaf((P).hf[3 * 64 + (i)], v4,                                   \
      fmaf((P).hf[2 * 64 + (i)], v3,                                   \
      fmaf((P).hf[1 * 64 + (i)], v2, (P).hf[0 * 64 + (i)] * v1))) )

// ---------------- fused kernel (64 cols x 64 rows per block, float2 per thread) ----------------
__global__ __launch_bounds__(256) void k_fused(const float* __restrict__ sig,
                                               const float* __restrict__ noise,
                                               float* __restrict__ out, FIX P,
                                               float b0, float b1, float b2, float b3, float b4,
                                               float na1, float na2, float na3, float na4) {
    __shared__ __align__(16) float nz2[68][66];  // pre-transposed noise [j][col]
    __shared__ __align__(16) float sg2[68][66];  // signal [j][col]; rows 0..63 reused as st
    __shared__ __align__(16) float vv[4][66];    // reconstructed entering state per col
    __shared__ __align__(16) float sua[4][66];   // first-half zero-state end state per col
    __shared__ float sds[68];
    int tx = threadIdx.x, ty = threadIdx.y;
    int cg = blockIdx.x, k = blockIdx.y;
    int col0 = cg * 64;
    int t0   = k * 64;
    int c2 = 2 * tx;                             // local col pair base

    // ---- load tiles ----
    #pragma unroll
    for (int i = 0; i < 8; i++) {
        int c = ty * 8 + i;
        const float* nrow = noise + (size_t)(col0 + c) * TPAD + t0;
        nz2[tx][c]      = nrow[tx];
        nz2[tx + 32][c] = nrow[tx + 32];
        if (tx < 4) nz2[tx + 64][c] = nrow[tx + 64];
    }
    #pragma unroll
    for (int j = 0; j < 9; j++) {
        int r = ty + 8 * j;
        if (r < 68) {
            int trow = t0 - 4 + r;
            if (trow >= 0) {
                sg2[r][tx]      = sig[(size_t)trow * BB + col0 + tx];
                sg2[r][tx + 32] = sig[(size_t)trow * BB + col0 + tx + 32];
            } else {
                sg2[r][tx] = 0.f;
                sg2[r][tx + 32] = 0.f;
            }
        }
    }
    int tid = ty * 32 + tx;
    if (tid < 68) sds[tid] = g_sd[t0 + tid];
    __syncthreads();

    // ---- FIR: sliding 5-tap window over rows 8ty..8ty+11, 2 cols, results in regs ----
    float2 acc[8];
    {
        int base = 8 * ty;
        float2 w0, w1, w2, w3, w4;
        #define XVAL(jj, dst) do {                                        \
            float sdv = sds[jj];                                          \
            float2 nv = *(const float2*)&nz2[jj][c2];                     \
            float2 gv = *(const float2*)&sg2[jj][c2];                     \
            dst.x = fmaf(sdv, nv.x, gv.x);                                \
            dst.y = fmaf(sdv, nv.y, gv.y);                                \
        } while (0)
        XVAL(base + 0, w0); XVAL(base + 1, w1);
        XVAL(base + 2, w2); XVAL(base + 3, w3);
        #pragma unroll
        for (int i = 0; i < 8; i++) {
            XVAL(base + i + 4, w4);
            float ax = b0 * w0.x;
            ax = fmaf(b1, w1.x, ax); ax = fmaf(b2, w2.x, ax);
            ax = fmaf(b3, w3.x, ax); ax = fmaf(b4, w4.x, ax);
            float ay = b0 * w0.y;
            ay = fmaf(b1, w1.y, ay); ay = fmaf(b2, w2.y, ay);
            ay = fmaf(b3, w3.y, ay); ay = fmaf(b4, w4.y, ay);
            acc[i] = make_float2(ax, ay);
            w0 = w1; w1 = w2; w2 = w3; w3 = w4;
        }
        #undef XVAL
    }
    __syncthreads();   // all sg2 reads done -> safe to overwrite with st
    #pragma unroll
    for (int i = 0; i < 8; i++)
        *(float2*)&sg2[8 * ty + i][c2] = acc[i];
    __syncthreads();   // st (in sg2) complete

    bool kz = (k == 0);
    if (ty == 0) {
        // ---- first-half zero-state scan (rows 0..31), 2 cols ----
        float2 p1 = *(float2*)&sg2[1][c2], p2 = *(float2*)&sg2[2][c2];
        float2 p3 = *(float2*)&sg2[3][c2], p4 = *(float2*)&sg2[4][c2];
        float2 y1 = {0.f,0.f}, y2 = {0.f,0.f}, y3 = {0.f,0.f}, y4 = {0.f,0.f};
        #pragma unroll
        for (int i = 0; i < 32; i++) {
            float2 sv = *(float2*)&sg2[i][c2];
            bool skip = kz && (i < 5);
            if (skip) { sv.x = 0.f; sv.y = 0.f; }
            float txv = fmaf(na4, y4.x, sv.x);
            txv = fmaf(na3, y3.x, txv); txv = fmaf(na2, y2.x, txv);
            float yx = fmaf(na1, y1.x, txv);
            float tyv = fmaf(na4, y4.y, sv.y);
            tyv = fmaf(na3, y3.y, tyv); tyv = fmaf(na2, y2.y, tyv);
            float yy = fmaf(na1, y1.y, tyv);
            if (!skip) *(float2*)&sg2[i][c2] = make_float2(yx, yy);
            y4 = y3; y3 = y2; y2 = y1; y1 = make_float2(yx, yy);
        }
        *(float2*)&sua[0][c2] = y1; *(float2*)&sua[1][c2] = y2;
        *(float2*)&sua[2][c2] = y3; *(float2*)&sua[3][c2] = y4;
        if (kz) {
            g_v0[col0 + c2]     = make_float4(p4.x, p3.x, p2.x, p1.x);
            g_v0[col0 + c2 + 1] = make_float4(p4.y, p3.y, p2.y, p1.y);
        }
        asm volatile("bar.sync 1, 64;" ::: "memory");
    } else if (ty == 1) {
        // ---- second-half zero-state scan (rows 32..63), 2 cols ----
        float2 y1 = {0.f,0.f}, y2 = {0.f,0.f}, y3 = {0.f,0.f}, y4 = {0.f,0.f};
        #pragma unroll
        for (int i = 32; i < 64; i++) {
            float2 sv = *(float2*)&sg2[i][c2];
            float txv = fmaf(na4, y4.x, sv.x);
            txv = fmaf(na3, y3.x, txv); txv = fmaf(na2, y2.x, txv);
            float yx = fmaf(na1, y1.x, txv);
            float tyv = fmaf(na4, y4.y, sv.y);
            tyv = fmaf(na3, y3.y, tyv); tyv = fmaf(na2, y2.y, tyv);
            float yy = fmaf(na1, y1.y, tyv);
            *(float2*)&sg2[i][c2] = make_float2(yx, yy);
            y4 = y3; y3 = y2; y2 = y1; y1 = make_float2(yx, yy);
        }
        asm volatile("bar.sync 1, 64;" ::: "memory");
        // ---- f64 combine (kills double-amplified rounding), per column ----
        float2 A1 = *(float2*)&sua[0][c2], A2 = *(float2*)&sua[1][c2];
        float2 A3 = *(float2*)&sua[2][c2], A4 = *(float2*)&sua[3][c2];
        {
            double a1 = A1.x, a2 = A2.x, a3 = A3.x, a4 = A4.x;
            double u1 = (double)y1.x + P.hfd[3]*a1 + P.hfd[7]*a2 + P.hfd[11]*a3 + P.hfd[15]*a4;
            double u2 = (double)y2.x + P.hfd[2]*a1 + P.hfd[6]*a2 + P.hfd[10]*a3 + P.hfd[14]*a4;
            double u3 = (double)y3.x + P.hfd[1]*a1 + P.hfd[5]*a2 + P.hfd[9]*a3  + P.hfd[13]*a4;
            double u4 = (double)y4.x + P.hfd[0]*a1 + P.hfd[4]*a2 + P.hfd[8]*a3  + P.hfd[12]*a4;
            g_u[k * BB + col0 + c2] = make_float4((float)u1, (float)u2, (float)u3, (float)u4);
        }
        {
            double a1 = A1.y, a2 = A2.y, a3 = A3.y, a4 = A4.y;
            double u1 = (double)y1.y + P.hfd[3]*a1 + P.hfd[7]*a2 + P.hfd[11]*a3 + P.hfd[15]*a4;
            double u2 = (double)y2.y + P.hfd[2]*a1 + P.hfd[6]*a2 + P.hfd[10]*a3 + P.hfd[14]*a4;
            double u3 = (double)y3.y + P.hfd[1]*a1 + P.hfd[5]*a2 + P.hfd[9]*a3  + P.hfd[13]*a4;
            double u4 = (double)y4.y + P.hfd[0]*a1 + P.hfd[4]*a2 + P.hfd[8]*a3  + P.hfd[12]*a4;
            g_u[k * BB + col0 + c2 + 1] = make_float4((float)u1, (float)u2, (float)u3, (float)u4);
        }
        __threadfence();
        __syncwarp();
        if (tx == 0) atomicExch(&g_flag[cg * NBLK + k], 1);
    } else if (ty == 2) {
        // ---- concurrent: reconstruct entering state v_k for 2 cols ----
        if (kz) {
            // rows 1..4 stay raw (warp0 skips those stores)
            *(float2*)&vv[0][c2] = *(float2*)&sg2[4][c2];
            *(float2*)&vv[1][c2] = *(float2*)&sg2[3][c2];
            *(float2*)&vv[2][c2] = *(float2*)&sg2[2][c2];
            *(float2*)&vv[3][c2] = *(float2*)&sg2[1][c2];
        } else {
            if (tx < 5) {
                int idx = k - 1 - tx;
                if (idx >= 0) {
                    volatile int* fp = (volatile int*)&g_flag[cg * NBLK + idx];
                    while (*fp == 0) __nanosleep(32);
                }
            }
            __syncwarp();
            __threadfence();

            float ax1 = 0.f, ax2 = 0.f, ax3 = 0.f, ax4 = 0.f;
            float bx1 = 0.f, bx2 = 0.f, bx3 = 0.f, bx4 = 0.f;
            #pragma unroll
            for (int j = 0; j <= 4; j++) {
                int idx = k - 1 - j;
                if (idx < 0) break;
                float4 ua = __ldcg(&g_u[idx * BB + col0 + c2]);
                float4 ub = __ldcg(&g_u[idx * BB + col0 + c2 + 1]);
                const float* m = P.m + j * 16;
                MV4(m, ua.x, ua.y, ua.z, ua.w, ax1, ax2, ax3, ax4);
                MV4(m, ub.x, ub.y, ub.z, ub.w, bx1, bx2, bx3, bx4);
            }
            if (k <= 5) {
                float4 ua = __ldcg(&g_v0[col0 + c2]);
                float4 ub = __ldcg(&g_v0[col0 + c2 + 1]);
                const float* m = P.ma + (k - 1) * 16;
                MV4(m, ua.x, ua.y, ua.z, ua.w, ax1, ax2, ax3, ax4);
                MV4(m, ub.x, ub.y, ub.z, ub.w, bx1, bx2, bx3, bx4);
            }
            *(float2*)&vv[0][c2] = make_float2(ax1, bx1);
            *(float2*)&vv[1][c2] = make_float2(ax2, bx2);
            *(float2*)&vv[2][c2] = make_float2(ax3, bx3);
            *(float2*)&vv[3][c2] = make_float2(ax4, bx4);
        }
    }
    __syncthreads();   // sg2 = zero-state outputs; vv = entering state; sua = half state

    // ---- epilogue: corrections via impulse tables, 2 cols per thread ----
    float2 v1 = *(float2*)&vv[0][c2], v2 = *(float2*)&vv[1][c2];
    float2 v3 = *(float2*)&vv[2][c2], v4 = *(float2*)&vv[3][c2];
    float2 a1 = {0.f,0.f}, a2 = {0.f,0.f}, a3 = {0.f,0.f}, a4 = {0.f,0.f};
    if (ty >= 4) {
        a1 = *(float2*)&sua[0][c2]; a2 = *(float2*)&sua[1][c2];
        a3 = *(float2*)&sua[2][c2]; a4 = *(float2*)&sua[3][c2];
    }
    #pragma unroll
    for (int i = 0; i < 8; i++) {
        int tt = 8 * ty + i;
        float2 stv = *(float2*)&sg2[tt][c2];
        float2 val;
        if (kz && tt < 5) {
            val = stv;                        // out rows 0..4 = s rows 0..4
        } else {
            int ii = kz ? tt - 5 : tt;        // warp-uniform
            float addx = HDOT(P, ii, v1.x, v2.x, v3.x, v4.x);
            float addy = HDOT(P, ii, v1.y, v2.y, v3.y, v4.y);
            if (ty >= 4) {
                addx += HDOT(P, tt - 32, a1.x, a2.x, a3.x, a4.x);
                addy += HDOT(P, tt - 32, a1.y, a2.y, a3.y, a4.y);
            }
            val = make_float2(stv.x + addx, stv.y + addy);
        }
        *(float2*)(out + (size_t)(t0 + tt) * BB + col0 + c2) = val;
    }
}

// ---------------- host: Butterworth design (exact replica of reference, f64) ----------------
static void compute_butter(double* bc, double* ac) {
    const double PI = 3.14159265358979323846264338327950288;
    const int order = 4;
    const double wn = 25e9 / (0.5 / 1e-12);   // 0.05
    double warped = 4.0 * tan(PI * wn / 2.0);
    std::complex<double> p[4];
    for (int k = 1; k <= order; k++) {
        double ang = PI * (2.0 * k + order - 1.0) / (2.0 * order);
        p[k - 1] = warped * std::complex<double>(cos(ang), sin(ang));
    }
    double gain = warped * warped * warped * warped;
    std::complex<double> fs2(4.0, 0.0);
    std::complex<double> pz[4], prod(1.0, 0.0);
    for (int i = 0; i < 4; i++) { pz[i] = (fs2 + p[i]) / (fs2 - p[i]); prod *= (fs2 - p[i]); }
    double gz = gain * std::real(std::complex<double>(1.0, 0.0) / prod);
    const double binom[5] = {1, 4, 6, 4, 1};
    for (int i = 0; i < 5; i++) bc[i] = gz * binom[i];
    std::complex<double> c[5] = {{1,0},{0,0},{0,0},{0,0},{0,0}};
    for (int i = 0; i < 4; i++)
        for (int j = i + 1; j >= 1; j--)
            c[j] -= pz[i] * c[j - 1];
    for (int i = 0; i < 5; i++) ac[i] = std::real(c[i]);
}

// A^n (companion of the IIR state [y1,y2,y3,y4]) via column simulation, f64
static void apow(const double* ac, int n, double* A) {
    for (int c = 0; c < 4; c++) {
        double y1 = (c == 0), y2 = (c == 1), y3 = (c == 2), y4 = (c == 3);
        for (int it = 0; it < n; it++) {
            double y = -(ac[1] * y1 + ac[2] * y2 + ac[3] * y3 + ac[4] * y4);
            y4 = y3; y3 = y2; y2 = y1; y1 = y;
        }
        A[0 * 4 + c] = y1; A[1 * 4 + c] = y2; A[2 * 4 + c] = y3; A[3 * 4 + c] = y4;
    }
}

static void matmul4(const double* X, const double* Y, double* Z) {
    for (int r = 0; r < 4; r++)
        for (int c = 0; c < 4; c++) {
            double acc = 0.0;
            for (int t = 0; t < 4; t++) acc += X[r * 4 + t] * Y[t * 4 + c];
            Z[r * 4 + c] = acc;
        }
}

extern "C" void kernel_launch(void* const* d_in, const int* in_sizes, int n_in,
                              void* d_out, int out_size) {
    const float* sig   = (const float*)d_in[0];   // (16384, 512) f32
    const float* noise = (const float*)d_in[1];   // (512, 1, 16388) f32
    float* out = (float*)d_out;                   // (16384, 512) f32

    double bc[5], ac[5];
    compute_butter(bc, ac);

    static FIX fx;
    // zero-input impulse tables hf_c[i], 64 steps (f64 master; f32 table + f64 rows 28..31)
    for (int c = 0; c < 4; c++) {
        double y1 = (c == 0), y2 = (c == 1), y3 = (c == 2), y4 = (c == 3);
        for (int i = 0; i < 64; i++) {
            double y = -(ac[1] * y1 + ac[2] * y2 + ac[3] * y3 + ac[4] * y4);
            fx.hf[c * 64 + i] = (float)y;
            if (i >= 28 && i <= 31) fx.hfd[c * 4 + (i - 28)] = y;
            y4 = y3; y3 = y2; y2 = y1; y1 = y;
        }
    }
    double A59[16], A64[16], Mj[16], tmp[16];
    apow(ac, 59, A59);
    apow(ac, 64, A64);
    for (int i = 0; i < 16; i++) Mj[i] = (i % 5 == 0) ? 1.0 : 0.0;   // M^0 = I
    for (int j = 0; j <= 4; j++) {
        for (int i = 0; i < 16; i++) fx.m[j * 16 + i] = (float)Mj[i];
        matmul4(Mj, A59, tmp);                   // ma[j] = M^j * A^59
        for (int i = 0; i < 16; i++) fx.ma[j * 16 + i] = (float)tmp[i];
        matmul4(Mj, A64, tmp);                   // Mj = M^{j+1}
        for (int i = 0; i < 16; i++) Mj[i] = tmp[i];
    }

    const double Qc = 1.602176563e-19, KBc = 1.3806488e-23, Tk = 300.0;
    const double BR = 5e10, DARK = 1e-10, RL = 1e6;
    double C1  = 2.0 * Qc * BR;
    double ADD = C1 * DARK + 4.0 * KBc * Tk * BR / RL;

    float na1 = (float)(-ac[1]), na2 = (float)(-ac[2]);
    float na3 = (float)(-ac[3]), na4 = (float)(-ac[4]);

    k_sd   <<<(TPAD + 15) / 16, 256>>>(sig, (float)C1, (float)ADD);
    k_fused<<<dim3(NCG, NBLK), dim3(32, 8)>>>(sig, noise, out, fx,
              (float)bc[0], (float)bc[1], (float)bc[2], (float)bc[3], (float)bc[4],
              na1, na2, na3, na4);
}

// round 16
// speedup vs baseline: 1.1873x; 1.0600x over previous
#include <cuda_runtime.h>
#include <math.h>
#include <complex>

// ---------------- problem constants ----------------
#define TT    16384          // time steps (output rows)
#define BB    512            // batch columns
#define TPAD  16388          // TT + K - 1 (K = 5)
#define NBLK  256            // IIR blocks: block k = rows 64k..64k+63 (block 0 IIR starts row 5)
#define NCG   8              // column groups of 64

// ---------------- device scratch (static, allocation-free) ----------------
__device__ float  g_sd[TPAD];           // noise std-dev per padded time step
__device__ float4 g_u[NBLK * BB];       // zero-state end states per (block,col)
__device__ float4 g_v0[BB];             // initial state v0 = [s4,s3,s2,s1] per col
__device__ int    g_flag[NCG * NBLK];   // release flags, zeroed each replay by k_sd

struct FIX {
    float  m[5 * 16];     // M^j (j=0..4), M = A^64, row-major 4x4   (applied to u)
    float  ma[5 * 16];    // M^i * A^59 (i=0..4)                      (applied to v0, i=k-1)
    float  hf[4 * 64];    // zero-input impulse tables hf_c[i], 64 steps (f32, epilogue)
    double hfd[16];       // hfd[c*4 + (i-28)] = h_c[i], i=28..31 in f64 (u-publish combine)
};

// ---------------- kernel 1: noise std-dev (2 rows per warp) + flag reset ----------------
__global__ __launch_bounds__(256) void k_sd(const float* __restrict__ sig,
                                            float c1, float addc) {
    if (blockIdx.x < NCG)
        g_flag[blockIdx.x * NBLK + threadIdx.x] = 0;

    int lane = threadIdx.x & 31;
    int t0 = blockIdx.x * 16 + (threadIdx.x >> 5) * 2;
    if (t0 >= TPAD) return;
    float s0 = 0.f, s1 = 0.f;
    if (t0 >= 4) {
        const float4* r0 = (const float4*)(sig + (size_t)(t0 - 4) * BB);
        float4 a = r0[lane], b = r0[lane + 32], c = r0[lane + 64], d = r0[lane + 96];
        s0 = ((a.x + a.y) + (a.z + a.w)) + ((b.x + b.y) + (b.z + b.w))
           + ((c.x + c.y) + (c.z + c.w)) + ((d.x + d.y) + (d.z + d.w));
    }
    int t1 = t0 + 1;
    if (t1 >= 4 && t1 < TPAD) {
        const float4* r1 = (const float4*)(sig + (size_t)(t1 - 4) * BB);
        float4 a = r1[lane], b = r1[lane + 32], c = r1[lane + 64], d = r1[lane + 96];
        s1 = ((a.x + a.y) + (a.z + a.w)) + ((b.x + b.y) + (b.z + b.w))
           + ((c.x + c.y) + (c.z + c.w)) + ((d.x + d.y) + (d.z + d.w));
    }
    #pragma unroll
    for (int o = 16; o; o >>= 1) {
        s0 += __shfl_down_sync(0xffffffffu, s0, o);
        s1 += __shfl_down_sync(0xffffffffu, s1, o);
    }
    if (lane == 0) {
        g_sd[t0] = sqrtf(fmaf(c1, s0 * (1.f / 512.f), addc));
        if (t1 < TPAD) g_sd[t1] = sqrtf(fmaf(c1, s1 * (1.f / 512.f), addc));
    }
}

// 4x4 matvec (row-major m), accumulate into (r1..r4)
#define MV4(m, x1, x2, x3, x4, r1, r2, r3, r4)                        \
    do {                                                              \
        r1 = fmaf((m)[0],  x1, r1); r1 = fmaf((m)[1],  x2, r1);       \
        r1 = fmaf((m)[2],  x3, r1); r1 = fmaf((m)[3],  x4, r1);       \
        r2 = fmaf((m)[4],  x1, r2); r2 = fmaf((m)[5],  x2, r2);       \
        r2 = fmaf((m)[6],  x3, r2); r2 = fmaf((m)[7],  x4, r2);       \
        r3 = fmaf((m)[8],  x1, r3); r3 = fmaf((m)[9],  x2, r3);       \
        r3 = fmaf((m)[10], x3, r3); r3 = fmaf((m)[11], x4, r3);       \
        r4 = fmaf((m)[12], x1, r4); r4 = fmaf((m)[13], x2, r4);       \
        r4 = fmaf((m)[14], x3, r4); r4 = fmaf((m)[15], x4, r4);       \
    } while (0)

// zero-input dot: sum_c hf_c[i] * v_c (scalar)
#define HDOT(P, i, v1, v2, v3, v4)                                     \
    ( fmaf((P).hf[3 * 64 + (i)], v4,                                   \
      fmaf((P).hf[2 * 64 + (i)], v3,                                   \
      fmaf((P).hf[1 * 64 + (i)], v2, (P).hf[0 * 64 + (i)] * v1))) )

// ---------------- fused kernel (64 cols x 64 rows per block, float2 per thread) ----------------
// Signal read directly from global (coalesced, no staging); nz2 reused as st after FIR.
__global__ __launch_bounds__(256) void k_fused(const float* __restrict__ sig,
                                               const float* __restrict__ noise,
                                               float* __restrict__ out, FIX P,
                                               float b0, float b1, float b2, float b3, float b4,
                                               float na1, float na2, float na3, float na4) {
    __shared__ __align__(16) float nz2[68][66];  // noise [j][col]; rows 0..63 reused as st
    __shared__ __align__(16) float vv[4][66];    // reconstructed entering state per col
    __shared__ __align__(16) float sua[4][66];   // first-half zero-state end state per col
    __shared__ float sds[68];
    int tx = threadIdx.x, ty = threadIdx.y;
    int cg = blockIdx.x, k = blockIdx.y;
    int col0 = cg * 64;
    int t0   = k * 64;
    int c2 = 2 * tx;                             // local col pair base

    // ---- stage noise (transposed) + sd ----
    #pragma unroll
    for (int i = 0; i < 8; i++) {
        int c = ty * 8 + i;
        const float* nrow = noise + (size_t)(col0 + c) * TPAD + t0;
        nz2[tx][c]      = nrow[tx];
        nz2[tx + 32][c] = nrow[tx + 32];
        if (tx < 4) nz2[tx + 64][c] = nrow[tx + 64];
    }
    int tid = ty * 32 + tx;
    if (tid < 68) sds[tid] = g_sd[t0 + tid];
    __syncthreads();

    // ---- FIR: sliding 5-tap window; noise from smem, signal straight from global ----
    float2 acc[8];
    {
        int base = 8 * ty;
        const float* sigp = sig + (size_t)(t0 - 4 + base) * BB + col0 + c2;
        float2 w0, w1, w2, w3, w4;
        #define XVAL(jj, dst) do {                                        \
            int trow = t0 - 4 + base + (jj);                              \
            float sdv = sds[base + (jj)];                                 \
            float2 nv = *(const float2*)&nz2[base + (jj)][c2];            \
            float2 gv = make_float2(0.f, 0.f);                            \
            if (trow >= 0) gv = *(const float2*)(sigp + (size_t)(jj) * BB); \
            dst.x = fmaf(sdv, nv.x, gv.x);                                \
            dst.y = fmaf(sdv, nv.y, gv.y);                                \
        } while (0)
        XVAL(0, w0); XVAL(1, w1); XVAL(2, w2); XVAL(3, w3);
        #pragma unroll
        for (int i = 0; i < 8; i++) {
            XVAL(i + 4, w4);
            float ax = b0 * w0.x;
            ax = fmaf(b1, w1.x, ax); ax = fmaf(b2, w2.x, ax);
            ax = fmaf(b3, w3.x, ax); ax = fmaf(b4, w4.x, ax);
            float ay = b0 * w0.y;
            ay = fmaf(b1, w1.y, ay); ay = fmaf(b2, w2.y, ay);
            ay = fmaf(b3, w3.y, ay); ay = fmaf(b4, w4.y, ay);
            acc[i] = make_float2(ax, ay);
            w0 = w1; w1 = w2; w2 = w3; w3 = w4;
        }
        #undef XVAL
    }
    __syncthreads();   // all nz2 noise reads done -> safe to overwrite with st
    #pragma unroll
    for (int i = 0; i < 8; i++)
        *(float2*)&nz2[8 * ty + i][c2] = acc[i];
    __syncthreads();   // st (in nz2) complete

    bool kz = (k == 0);
    if (ty == 0) {
        // ---- first-half zero-state scan (rows 0..31), 2 cols ----
        float2 p1 = *(float2*)&nz2[1][c2], p2 = *(float2*)&nz2[2][c2];
        float2 p3 = *(float2*)&nz2[3][c2], p4 = *(float2*)&nz2[4][c2];
        float2 y1 = {0.f,0.f}, y2 = {0.f,0.f}, y3 = {0.f,0.f}, y4 = {0.f,0.f};
        #pragma unroll
        for (int i = 0; i < 32; i++) {
            float2 sv = *(float2*)&nz2[i][c2];
            bool skip = kz && (i < 5);
            if (skip) { sv.x = 0.f; sv.y = 0.f; }
            float txv = fmaf(na4, y4.x, sv.x);
            txv = fmaf(na3, y3.x, txv); txv = fmaf(na2, y2.x, txv);
            float yx = fmaf(na1, y1.x, txv);
            float tyv = fmaf(na4, y4.y, sv.y);
            tyv = fmaf(na3, y3.y, tyv); tyv = fmaf(na2, y2.y, tyv);
            float yy = fmaf(na1, y1.y, tyv);
            if (!skip) *(float2*)&nz2[i][c2] = make_float2(yx, yy);
            y4 = y3; y3 = y2; y2 = y1; y1 = make_float2(yx, yy);
        }
        *(float2*)&sua[0][c2] = y1; *(float2*)&sua[1][c2] = y2;
        *(float2*)&sua[2][c2] = y3; *(float2*)&sua[3][c2] = y4;
        if (kz) {
            g_v0[col0 + c2]     = make_float4(p4.x, p3.x, p2.x, p1.x);
            g_v0[col0 + c2 + 1] = make_float4(p4.y, p3.y, p2.y, p1.y);
        }
        asm volatile("bar.sync 1, 64;" ::: "memory");
    } else if (ty == 1) {
        // ---- second-half zero-state scan (rows 32..63), 2 cols ----
        float2 y1 = {0.f,0.f}, y2 = {0.f,0.f}, y3 = {0.f,0.f}, y4 = {0.f,0.f};
        #pragma unroll
        for (int i = 32; i < 64; i++) {
            float2 sv = *(float2*)&nz2[i][c2];
            float txv = fmaf(na4, y4.x, sv.x);
            txv = fmaf(na3, y3.x, txv); txv = fmaf(na2, y2.x, txv);
            float yx = fmaf(na1, y1.x, txv);
            float tyv = fmaf(na4, y4.y, sv.y);
            tyv = fmaf(na3, y3.y, tyv); tyv = fmaf(na2, y2.y, tyv);
            float yy = fmaf(na1, y1.y, tyv);
            *(float2*)&nz2[i][c2] = make_float2(yx, yy);
            y4 = y3; y3 = y2; y2 = y1; y1 = make_float2(yx, yy);
        }
        asm volatile("bar.sync 1, 64;" ::: "memory");
        // ---- f64 combine (kills double-amplified rounding), per column ----
        float2 A1 = *(float2*)&sua[0][c2], A2 = *(float2*)&sua[1][c2];
        float2 A3 = *(float2*)&sua[2][c2], A4 = *(float2*)&sua[3][c2];
        {
            double a1 = A1.x, a2 = A2.x, a3 = A3.x, a4 = A4.x;
            double u1 = (double)y1.x + P.hfd[3]*a1 + P.hfd[7]*a2 + P.hfd[11]*a3 + P.hfd[15]*a4;
            double u2 = (double)y2.x + P.hfd[2]*a1 + P.hfd[6]*a2 + P.hfd[10]*a3 + P.hfd[14]*a4;
            double u3 = (double)y3.x + P.hfd[1]*a1 + P.hfd[5]*a2 + P.hfd[9]*a3  + P.hfd[13]*a4;
            double u4 = (double)y4.x + P.hfd[0]*a1 + P.hfd[4]*a2 + P.hfd[8]*a3  + P.hfd[12]*a4;
            g_u[k * BB + col0 + c2] = make_float4((float)u1, (float)u2, (float)u3, (float)u4);
        }
        {
            double a1 = A1.y, a2 = A2.y, a3 = A3.y, a4 = A4.y;
            double u1 = (double)y1.y + P.hfd[3]*a1 + P.hfd[7]*a2 + P.hfd[11]*a3 + P.hfd[15]*a4;
            double u2 = (double)y2.y + P.hfd[2]*a1 + P.hfd[6]*a2 + P.hfd[10]*a3 + P.hfd[14]*a4;
            double u3 = (double)y3.y + P.hfd[1]*a1 + P.hfd[5]*a2 + P.hfd[9]*a3  + P.hfd[13]*a4;
            double u4 = (double)y4.y + P.hfd[0]*a1 + P.hfd[4]*a2 + P.hfd[8]*a3  + P.hfd[12]*a4;
            g_u[k * BB + col0 + c2 + 1] = make_float4((float)u1, (float)u2, (float)u3, (float)u4);
        }
        __threadfence();
        __syncwarp();
        if (tx == 0) atomicExch(&g_flag[cg * NBLK + k], 1);
    } else if (ty == 2) {
        // ---- concurrent: reconstruct entering state v_k for 2 cols ----
        if (kz) {
            // rows 1..4 stay raw (warp0 skips those stores)
            *(float2*)&vv[0][c2] = *(float2*)&nz2[4][c2];
            *(float2*)&vv[1][c2] = *(float2*)&nz2[3][c2];
            *(float2*)&vv[2][c2] = *(float2*)&nz2[2][c2];
            *(float2*)&vv[3][c2] = *(float2*)&nz2[1][c2];
        } else {
            if (tx < 5) {
                int idx = k - 1 - tx;
                if (idx >= 0) {
                    volatile int* fp = (volatile int*)&g_flag[cg * NBLK + idx];
                    while (*fp == 0) __nanosleep(32);
                }
            }
            __syncwarp();
            __threadfence();

            float ax1 = 0.f, ax2 = 0.f, ax3 = 0.f, ax4 = 0.f;
            float bx1 = 0.f, bx2 = 0.f, bx3 = 0.f, bx4 = 0.f;
            #pragma unroll
            for (int j = 0; j <= 4; j++) {
                int idx = k - 1 - j;
                if (idx < 0) break;
                float4 ua = __ldcg(&g_u[idx * BB + col0 + c2]);
                float4 ub = __ldcg(&g_u[idx * BB + col0 + c2 + 1]);
                const float* m = P.m + j * 16;
                MV4(m, ua.x, ua.y, ua.z, ua.w, ax1, ax2, ax3, ax4);
                MV4(m, ub.x, ub.y, ub.z, ub.w, bx1, bx2, bx3, bx4);
            }
            if (k <= 5) {
                float4 ua = __ldcg(&g_v0[col0 + c2]);
                float4 ub = __ldcg(&g_v0[col0 + c2 + 1]);
                const float* m = P.ma + (k - 1) * 16;
                MV4(m, ua.x, ua.y, ua.z, ua.w, ax1, ax2, ax3, ax4);
                MV4(m, ub.x, ub.y, ub.z, ub.w, bx1, bx2, bx3, bx4);
            }
            *(float2*)&vv[0][c2] = make_float2(ax1, bx1);
            *(float2*)&vv[1][c2] = make_float2(ax2, bx2);
            *(float2*)&vv[2][c2] = make_float2(ax3, bx3);
            *(float2*)&vv[3][c2] = make_float2(ax4, bx4);
        }
    }
    __syncthreads();   // nz2 = zero-state outputs; vv = entering state; sua = half state

    // ---- epilogue: corrections via impulse tables, 2 cols per thread ----
    float2 v1 = *(float2*)&vv[0][c2], v2 = *(float2*)&vv[1][c2];
    float2 v3 = *(float2*)&vv[2][c2], v4 = *(float2*)&vv[3][c2];
    float2 a1 = {0.f,0.f}, a2 = {0.f,0.f}, a3 = {0.f,0.f}, a4 = {0.f,0.f};
    if (ty >= 4) {
        a1 = *(float2*)&sua[0][c2]; a2 = *(float2*)&sua[1][c2];
        a3 = *(float2*)&sua[2][c2]; a4 = *(float2*)&sua[3][c2];
    }
    #pragma unroll
    for (int i = 0; i < 8; i++) {
        int tt = 8 * ty + i;
        float2 stv = *(float2*)&nz2[tt][c2];
        float2 val;
        if (kz && tt < 5) {
            val = stv;                        // out rows 0..4 = s rows 0..4
        } else {
            int ii = kz ? tt - 5 : tt;        // warp-uniform
            float addx = HDOT(P, ii, v1.x, v2.x, v3.x, v4.x);
            float addy = HDOT(P, ii, v1.y, v2.y, v3.y, v4.y);
            if (ty >= 4) {
                addx += HDOT(P, tt - 32, a1.x, a2.x, a3.x, a4.x);
                addy += HDOT(P, tt - 32, a1.y, a2.y, a3.y, a4.y);
            }
            val = make_float2(stv.x + addx, stv.y + addy);
        }
        *(float2*)(out + (size_t)(t0 + tt) * BB + col0 + c2) = val;
    }
}

// ---------------- host: Butterworth design (exact replica of reference, f64) ----------------
static void compute_butter(double* bc, double* ac) {
    const double PI = 3.14159265358979323846264338327950288;
    const int order = 4;
    const double wn = 25e9 / (0.5 / 1e-12);   // 0.05
    double warped = 4.0 * tan(PI * wn / 2.0);
    std::complex<double> p[4];
    for (int k = 1; k <= order; k++) {
        double ang = PI * (2.0 * k + order - 1.0) / (2.0 * order);
        p[k - 1] = warped * std::complex<double>(cos(ang), sin(ang));
    }
    double gain = warped * warped * warped * warped;
    std::complex<double> fs2(4.0, 0.0);
    std::complex<double> pz[4], prod(1.0, 0.0);
    for (int i = 0; i < 4; i++) { pz[i] = (fs2 + p[i]) / (fs2 - p[i]); prod *= (fs2 - p[i]); }
    double gz = gain * std::real(std::complex<double>(1.0, 0.0) / prod);
    const double binom[5] = {1, 4, 6, 4, 1};
    for (int i = 0; i < 5; i++) bc[i] = gz * binom[i];
    std::complex<double> c[5] = {{1,0},{0,0},{0,0},{0,0},{0,0}};
    for (int i = 0; i < 4; i++)
        for (int j = i + 1; j >= 1; j--)
            c[j] -= pz[i] * c[j - 1];
    for (int i = 0; i < 5; i++) ac[i] = std::real(c[i]);
}

// A^n (companion of the IIR state [y1,y2,y3,y4]) via column simulation, f64
static void apow(const double* ac, int n, double* A) {
    for (int c = 0; c < 4; c++) {
        double y1 = (c == 0), y2 = (c == 1), y3 = (c == 2), y4 = (c == 3);
        for (int it = 0; it < n; it++) {
            double y = -(ac[1] * y1 + ac[2] * y2 + ac[3] * y3 + ac[4] * y4);
            y4 = y3; y3 = y2; y2 = y1; y1 = y;
        }
        A[0 * 4 + c] = y1; A[1 * 4 + c] = y2; A[2 * 4 + c] = y3; A[3 * 4 + c] = y4;
    }
}

static void matmul4(const double* X, const double* Y, double* Z) {
    for (int r = 0; r < 4; r++)
        for (int c = 0; c < 4; c++) {
            double acc = 0.0;
            for (int t = 0; t < 4; t++) acc += X[r * 4 + t] * Y[t * 4 + c];
            Z[r * 4 + c] = acc;
        }
}

extern "C" void kernel_launch(void* const* d_in, const int* in_sizes, int n_in,
                              void* d_out, int out_size) {
    const float* sig   = (const float*)d_in[0];   // (16384, 512) f32
    const float* noise = (const float*)d_in[1];   // (512, 1, 16388) f32
    float* out = (float*)d_out;                   // (16384, 512) f32

    double bc[5], ac[5];
    compute_butter(bc, ac);

    static FIX fx;
    // zero-input impulse tables hf_c[i], 64 steps (f64 master; f32 table + f64 rows 28..31)
    for (int c = 0; c < 4; c++) {
        double y1 = (c == 0), y2 = (c == 1), y3 = (c == 2), y4 = (c == 3);
        for (int i = 0; i < 64; i++) {
            double y = -(ac[1] * y1 + ac[2] * y2 + ac[3] * y3 + ac[4] * y4);
            fx.hf[c * 64 + i] = (float)y;
            if (i >= 28 && i <= 31) fx.hfd[c * 4 + (i - 28)] = y;
            y4 = y3; y3 = y2; y2 = y1; y1 = y;
        }
    }
    double A59[16], A64[16], Mj[16], tmp[16];
    apow(ac, 59, A59);
    apow(ac, 64, A64);
    for (int i = 0; i < 16; i++) Mj[i] = (i % 5 == 0) ? 1.0 : 0.0;   // M^0 = I
    for (int j = 0; j <= 4; j++) {
        for (int i = 0; i < 16; i++) fx.m[j * 16 + i] = (float)Mj[i];
        matmul4(Mj, A59, tmp);                   // ma[j] = M^j * A^59
        for (int i = 0; i < 16; i++) fx.ma[j * 16 + i] = (float)tmp[i];
        matmul4(Mj, A64, tmp);                   // Mj = M^{j+1}
        for (int i = 0; i < 16; i++) Mj[i] = tmp[i];
    }

    const double Qc = 1.602176563e-19, KBc = 1.3806488e-23, Tk = 300.0;
    const double BR = 5e10, DARK = 1e-10, RL = 1e6;
    double C1  = 2.0 * Qc * BR;
    double ADD = C1 * DARK + 4.0 * KBc * Tk * BR / RL;

    float na1 = (float)(-ac[1]), na2 = (float)(-ac[2]);
    float na3 = (float)(-ac[3]), na4 = (float)(-ac[4]);

    k_sd   <<<(TPAD + 15) / 16, 256>>>(sig, (float)C1, (float)ADD);
    k_fused<<<dim3(NCG, NBLK), dim3(32, 8)>>>(sig, noise, out, fx,
              (float)bc[0], (float)bc[1], (float)bc[2], (float)bc[3], (float)bc[4],
              na1, na2, na3, na4);
}